// round 4
// baseline (speedup 1.0000x reference)
#include <cuda_runtime.h>
#include <math.h>

#define BB   32
#define NNV  64
#define FF   1280
#define HH   512
#define EE   512
#define VV   10000
#define TT   80
#define SOS_ID 1
#define EF   1792
#define A2K  2304
#define G4H  2048

#define DOUT_H    (BB*TT*VV)
#define DOUT_C    (DOUT_H + BB*HH)
#define DOUT_ATTN (DOUT_C + BB*HH)

#define NLOGIT_TILES 157
#define NLIN_TILES   28

__device__ float g_h[BB*HH];
__device__ float g_c[BB*HH];
__device__ float g_a2[BB*A2K];            // [x 512 | context 1280 | h 512]
__device__ float g_lin[BB*EF];            // [h@W1 512 | h@Wg 1280]
__device__ float g_gpart[9*BB*G4H];       // split-K partials for gates GEMM
__device__ float g_mean[BB*FF];
__device__ float g_epT[BB*HH*NNV];        // enc_proj transposed [b][k][n]
__device__ unsigned long long g_argkey[BB];

__device__ __forceinline__ unsigned int f2ord(float v) {
    unsigned int u = __float_as_uint(v);
    return (u & 0x80000000u) ? ~u : (u | 0x80000000u);
}

// Load A[32][k0..k0+256) transposed into As[k][r], pad 33.
__device__ __forceinline__ void loadA(const float* __restrict__ A, int lda, int k0,
                                      float (*As)[33]) {
#pragma unroll
    for (int i = 0; i < 32; ++i) {
        int t = threadIdx.x + i * 256;
        int r = t >> 8, k = t & 255;
        As[k][r] = A[(size_t)r * lda + k0 + k];
    }
}

// 32x64 tile, 256 K. q=tid&15 -> col quad, rp=tid>>4 -> rows 2rp,2rp+1.
__device__ __forceinline__ void mma256(const float* __restrict__ Wk0, int ldw,
                                       int col, bool jv,
                                       const float (*As)[33], int r0, float acc[8]) {
#pragma unroll 8
    for (int k = 0; k < 256; ++k) {
        float4 w = jv ? *reinterpret_cast<const float4*>(Wk0 + (size_t)k * ldw + col)
                      : make_float4(0.f,0.f,0.f,0.f);
        float a0 = As[k][r0], a1 = As[k][r0+1];
        acc[0]=fmaf(a0,w.x,acc[0]); acc[1]=fmaf(a0,w.y,acc[1]);
        acc[2]=fmaf(a0,w.z,acc[2]); acc[3]=fmaf(a0,w.w,acc[3]);
        acc[4]=fmaf(a1,w.x,acc[4]); acc[5]=fmaf(a1,w.y,acc[5]);
        acc[6]=fmaf(a1,w.z,acc[6]); acc[7]=fmaf(a1,w.w,acc[7]);
    }
}

// ---- setup: mean feature, x0 = emb[SOS] ----
__global__ void kInit(const float* __restrict__ feat, const float* __restrict__ emb) {
    int gid = blockIdx.x * 256 + threadIdx.x, stride = gridDim.x * 256;
    for (int i = gid; i < BB*FF; i += stride) {
        int b = i / FF, j = i % FF;
        float s = 0.f;
        for (int n = 0; n < NNV; ++n) s += feat[((size_t)b*NNV + n)*FF + j];
        g_mean[i] = s * (1.f/64.f);
    }
    for (int i = gid; i < BB*EE; i += stride) {
        int b = i >> 9, e = i & 511;
        g_a2[b*A2K + e] = emb[(size_t)SOS_ID*EE + e];
    }
    if (gid < BB) g_argkey[gid] = 0ull;
}

// ---- h0/c0: mean[32,1280] @ Wh/Wc, 16 blocks, full K per block (deterministic) ----
__global__ void __launch_bounds__(256) kInitHC(const float* __restrict__ Wh,
                                               const float* __restrict__ Wc) {
    __shared__ float As[256][33];
    int mat = blockIdx.x >> 3, tile = blockIdx.x & 7;
    const float* W = mat ? Wc : Wh;
    float* out = mat ? g_c : g_h;
    int tid = threadIdx.x, q = tid & 15, r0 = (tid >> 4) * 2;
    int j = tile * 64 + q * 4;
    float acc[8] = {0,0,0,0,0,0,0,0};
    for (int k0 = 0; k0 < FF; k0 += 256) {
        __syncthreads();
        loadA(g_mean, FF, k0, As);
        __syncthreads();
        mma256(W + (size_t)k0 * HH, HH, j, true, As, r0, acc);
    }
#pragma unroll
    for (int cc = 0; cc < 4; ++cc) {
        out[r0*HH + j + cc]     = acc[cc];
        out[(r0+1)*HH + j + cc] = acc[4+cc];
    }
}

__global__ void kHCBias(const float* __restrict__ bh, const float* __restrict__ bc) {
    int idx = blockIdx.x * 256 + threadIdx.x;
    int b = idx >> 9, u = idx & 511;
    float h = g_h[idx] + bh[u];
    g_h[idx] = h;
    g_a2[b*A2K + EF + u] = h;
    g_c[idx] += bc[u];
}

// ---- enc_proj = feat @ W2 + b2 stored transposed [b][k][n] ----
__global__ void __launch_bounds__(256) kEncProj(const float* __restrict__ feat,
                                                const float* __restrict__ W2,
                                                const float* __restrict__ b2) {
    __shared__ float As[128][65];
    int tid = threadIdx.x, rt = blockIdx.x, ct = blockIdx.y;
    int q = tid & 15, rr = tid >> 4;
    float acc[16];
#pragma unroll
    for (int i = 0; i < 16; ++i) acc[i] = 0.f;
    int row0 = rt * 64;
    for (int k0 = 0; k0 < FF; k0 += 128) {
        __syncthreads();
        for (int tt = tid; tt < 64*128; tt += 256) {
            int r = tt >> 7, k = tt & 127;
            As[k][r] = feat[(size_t)(row0 + r)*FF + k0 + k];
        }
        __syncthreads();
        const float* Wp = W2 + (size_t)k0 * HH + ct*64 + q*4;
#pragma unroll 4
        for (int k = 0; k < 128; ++k) {
            float4 w = *reinterpret_cast<const float4*>(Wp + (size_t)k * HH);
#pragma unroll
            for (int rrr = 0; rrr < 4; ++rrr) {
                float a = As[k][rr*4 + rrr];
                acc[rrr*4+0]=fmaf(a,w.x,acc[rrr*4+0]);
                acc[rrr*4+1]=fmaf(a,w.y,acc[rrr*4+1]);
                acc[rrr*4+2]=fmaf(a,w.z,acc[rrr*4+2]);
                acc[rrr*4+3]=fmaf(a,w.w,acc[rrr*4+3]);
            }
        }
    }
#pragma unroll
    for (int rrr = 0; rrr < 4; ++rrr) {
        int row = row0 + rr*4 + rrr;
        int b = row >> 6, nidx = row & 63;
#pragma unroll
        for (int cc = 0; cc < 4; ++cc) {
            int j = ct*64 + q*4 + cc;
            g_epT[((size_t)b*HH + j)*NNV + nidx] = acc[rrr*4+cc] + b2[j];
        }
    }
}

// ---- per step: attention scores + softmax + gated context (one block per batch) ----
__global__ void __launch_bounds__(256) kAttnCtx(const float* __restrict__ feat,
                                                const float* __restrict__ b1,
                                                const float* __restrict__ Va,
                                                const float* __restrict__ bVa,
                                                const float* __restrict__ bg,
                                                float* __restrict__ dout, int t) {
    __shared__ float hq[HH], va[HH];
    __shared__ float part[4][NNV], wsh[NNV];
    __shared__ float redm[2], reds[2];
    int b = blockIdx.x, tid = threadIdx.x;
    for (int i = tid; i < HH; i += 256) {
        hq[i] = g_lin[b*EF + i] + b1[i];
        va[i] = Va[i];
    }
    __syncthreads();
    int n = tid & 63, p = tid >> 6;
    const float* ep = g_epT + (size_t)b * HH * NNV;
    float s = 0.f;
    for (int k = p*128; k < p*128 + 128; ++k)
        s = fmaf(fmaxf(hq[k] + ep[(size_t)k*NNV + n], 0.f), va[k], s);
    part[p][n] = s;
    __syncthreads();
    float sc = -1e30f;
    if (tid < NNV) sc = part[0][tid]+part[1][tid]+part[2][tid]+part[3][tid] + bVa[0];
    float m = sc;
#pragma unroll
    for (int d = 16; d >= 1; d >>= 1) m = fmaxf(m, __shfl_xor_sync(0xFFFFFFFFu, m, d));
    if (tid < NNV && (tid & 31) == 0) redm[tid >> 5] = m;
    __syncthreads();
    float gm = fmaxf(redm[0], redm[1]);
    float e = (tid < NNV) ? expf(sc - gm) : 0.f;
    float ss = e;
#pragma unroll
    for (int d = 16; d >= 1; d >>= 1) ss += __shfl_xor_sync(0xFFFFFFFFu, ss, d);
    if (tid < NNV && (tid & 31) == 0) reds[tid >> 5] = ss;
    __syncthreads();
    float tot = reds[0] + reds[1];
    if (tid < NNV) {
        float w = e / tot;
        wsh[tid] = w;
        dout[DOUT_ATTN + (size_t)b*TT*NNV + (size_t)t*NNV + tid] = w;
    }
    __syncthreads();
#pragma unroll
    for (int ch = 0; ch < 5; ++ch) {
        int j = ch*256 + tid;
        const float* fb = feat + (size_t)b*NNV*FF + j;
        float cs = 0.f;
#pragma unroll 8
        for (int nn = 0; nn < NNV; ++nn) cs = fmaf(wsh[nn], fb[(size_t)nn*FF], cs);
        float gp = g_lin[b*EF + HH + j] + bg[j];
        float gate = 1.f / (1.f + expf(-gp));
        g_a2[b*A2K + EE + j] = cs * gate;
    }
}

// ---- gates GEMM [32,2304]@[2304,2048] split-K x9 -> partial buffers ----
__global__ void __launch_bounds__(256) kGates(const float* __restrict__ Wx,
                                              const float* __restrict__ Whh) {
    __shared__ float As[256][33];
    int tid = threadIdx.x, q = tid & 15, r0 = (tid >> 4) * 2;
    int tile = blockIdx.x & 31, ck = blockIdx.x >> 5;
    int k0 = ck * 256;
    const float* Wp = (ck < 7) ? (Wx + (size_t)k0 * G4H)
                               : (Whh + (size_t)(k0 - EF) * G4H);
    int j = tile*64 + q*4;
    float acc[8] = {0,0,0,0,0,0,0,0};
    loadA(g_a2, A2K, k0, As);
    __syncthreads();
    mma256(Wp, G4H, j, true, As, r0, acc);
    float* out = g_gpart + (size_t)ck * BB * G4H;
#pragma unroll
    for (int cc = 0; cc < 4; ++cc) {
        out[r0*G4H + j + cc]     = acc[cc];
        out[(r0+1)*G4H + j + cc] = acc[4+cc];
    }
}

// ---- LSTM elementwise (fixed-order split-K reduce; deterministic) ----
__global__ void kLstm(const float* __restrict__ blstm, float* __restrict__ dout, int t) {
    int idx = blockIdx.x * 256 + threadIdx.x;  // < 16384
    int b = idx >> 9, u = idx & 511;
    float gv4[4];
#pragma unroll
    for (int g = 0; g < 4; ++g) {
        int col = g*512 + u;
        float s = blstm[col];
#pragma unroll
        for (int ck = 0; ck < 9; ++ck)
            s += g_gpart[(size_t)ck*BB*G4H + b*G4H + col];
        gv4[g] = s;
    }
    float c = g_c[idx];
    float si = 1.f / (1.f + expf(-gv4[0]));
    float sf = 1.f / (1.f + expf(-gv4[1]));
    float so = 1.f / (1.f + expf(-gv4[3]));
    float c2 = sf * c + si * tanhf(gv4[2]);
    float h2 = so * tanhf(c2);
    g_c[idx] = c2;
    g_h[idx] = h2;
    g_a2[b*A2K + EF + u] = h2;
    if (t == TT-1) { dout[DOUT_H + idx] = h2; dout[DOUT_C + idx] = c2; }
    if (blockIdx.x == 0 && threadIdx.x < BB) g_argkey[threadIdx.x] = 0ull;
}

// ---- logits + argmax (int-key atomicMax), plus next-step h@[W1|Wg] tiles ----
__global__ void __launch_bounds__(256) kOutLin(const float* __restrict__ Wout,
                                               const float* __restrict__ bout,
                                               const float* __restrict__ W1,
                                               const float* __restrict__ Wg,
                                               float* __restrict__ dout,
                                               int t, int full) {
    __shared__ float As[256][33];
    __shared__ unsigned long long skey[BB];
    int tid = threadIdx.x, q = tid & 15, r0 = (tid >> 4) * 2;
    int bid = blockIdx.x;
    float acc[8] = {0,0,0,0,0,0,0,0};
    bool isLogit = full && (bid < NLOGIT_TILES);
    if (isLogit) {
        if (tid < BB) skey[tid] = 0ull;
        int jq = bid*64 + q*4;
        bool jv = jq < VV;
        for (int k0 = 0; k0 < HH; k0 += 256) {
            __syncthreads();
            loadA(g_h, HH, k0, As);
            __syncthreads();
            mma256(Wout + (size_t)k0 * VV, VV, jq, jv, As, r0, acc);
        }
        if (jv) {
            unsigned long long k0_ = 0ull, k1_ = 0ull;
#pragma unroll
            for (int cc = 0; cc < 4; ++cc) {
                int j = jq + cc;
                float bo = bout[j];
                float v0 = acc[cc] + bo, v1 = acc[4+cc] + bo;
                dout[(size_t)r0*TT*VV + (size_t)t*VV + j] = v0;
                dout[(size_t)(r0+1)*TT*VV + (size_t)t*VV + j] = v1;
                unsigned long long kk0 = ((unsigned long long)f2ord(v0) << 32) | (unsigned)(~j);
                unsigned long long kk1 = ((unsigned long long)f2ord(v1) << 32) | (unsigned)(~j);
                if (kk0 > k0_) k0_ = kk0;
                if (kk1 > k1_) k1_ = kk1;
            }
            atomicMax(&skey[r0], k0_);
            atomicMax(&skey[r0+1], k1_);
        }
        __syncthreads();
        if (tid < BB && skey[tid]) atomicMax(&g_argkey[tid], skey[tid]);
    } else {
        int tile = full ? (bid - NLOGIT_TILES) : bid;
        int j = tile*64 + q*4;
        const float* W; int ldw, col;
        if (tile < 8) { W = W1; ldw = HH; col = j; }
        else          { W = Wg; ldw = FF; col = j - HH; }
        for (int k0 = 0; k0 < HH; k0 += 256) {
            __syncthreads();
            loadA(g_h, HH, k0, As);
            __syncthreads();
            mma256(W + (size_t)k0 * ldw, ldw, col, true, As, r0, acc);
        }
#pragma unroll
        for (int cc = 0; cc < 4; ++cc) {
            g_lin[r0*EF + j + cc]     = acc[cc];
            g_lin[(r0+1)*EF + j + cc] = acc[4+cc];
        }
    }
}

// ---- embedding gather of argmax token ----
__global__ void kEmb(const float* __restrict__ emb) {
    int b = blockIdx.x;
    unsigned long long key = g_argkey[b];
    int idx = (int)(~((unsigned)(key & 0xFFFFFFFFu)));
    for (int e = threadIdx.x; e < EE; e += 256)
        g_a2[b*A2K + e] = emb[(size_t)idx*EE + e];
}

extern "C" void kernel_launch(void* const* d_in, const int* in_sizes, int n_in,
                              void* d_out, int out_size) {
    // input order: feature_outputs, caption, [max_caption], emb, W1, b1, W2, b2,
    //              Va, bVa, Wh, bh, Wc, bc, Wg, bg, Wx, Whh, blstm, Wout, bout
    int base = (n_in >= 3 && in_sizes[2] == 1) ? 3 : 2;
    const float* feat = (const float*)d_in[0];
    const float* emb  = (const float*)d_in[base+0];
    const float* W1   = (const float*)d_in[base+1];
    const float* b1   = (const float*)d_in[base+2];
    const float* W2   = (const float*)d_in[base+3];
    const float* b2   = (const float*)d_in[base+4];
    const float* Va   = (const float*)d_in[base+5];
    const float* bVa  = (const float*)d_in[base+6];
    const float* Wh   = (const float*)d_in[base+7];
    const float* bh   = (const float*)d_in[base+8];
    const float* Wc   = (const float*)d_in[base+9];
    const float* bc   = (const float*)d_in[base+10];
    const float* Wg   = (const float*)d_in[base+11];
    const float* bg   = (const float*)d_in[base+12];
    const float* Wx   = (const float*)d_in[base+13];
    const float* Whh  = (const float*)d_in[base+14];
    const float* blstm= (const float*)d_in[base+15];
    const float* Wout = (const float*)d_in[base+16];
    const float* bout = (const float*)d_in[base+17];
    float* dout = (float*)d_out;

    kInit<<<160, 256>>>(feat, emb);
    kInitHC<<<16, 256>>>(Wh, Wc);
    kHCBias<<<64, 256>>>(bh, bc);
    kEncProj<<<dim3(32, 8), 256>>>(feat, W2, b2);
    kOutLin<<<NLIN_TILES, 256>>>(Wout, bout, W1, Wg, dout, 0, 0);  // lin for h0

    for (int t = 0; t < TT; ++t) {
        kAttnCtx<<<BB, 256>>>(feat, b1, Va, bVa, bg, dout, t);
        kGates<<<288, 256>>>(Wx, Whh);
        kLstm<<<64, 256>>>(blstm, dout, t);
        kOutLin<<<NLOGIT_TILES + NLIN_TILES, 256>>>(Wout, bout, W1, Wg, dout, t, 1);
        kEmb<<<BB, 256>>>(emb);
    }
}

// round 7
// speedup vs baseline: 1.0059x; 1.0059x over previous
#include <cuda_runtime.h>
#include <math.h>

#define BB   32
#define NNV  64
#define FF   1280
#define HH   512
#define EE   512
#define VV   10000
#define TT   80
#define SOS_ID 1
#define EF   1792
#define A2K  2304
#define G4H  2048
#define NBLK 148

#define DOUT_H    (BB*TT*VV)
#define DOUT_C    (DOUT_H + BB*HH)
#define DOUT_ATTN (DOUT_C + BB*HH)

#define NLOGIT_TILES 157

typedef unsigned long long u64;

__device__ float g_h[BB*HH];
__device__ float g_c[BB*HH];
__device__ float g_a2[BB*A2K];            // [x 512 | ctx 1280 | h 512]
__device__ float g_lin[BB*EF];            // [h@W1 512 | h@Wg 1280]
__device__ float g_gpart[9*BB*G4H];
__device__ float g_mean[BB*FF];
__device__ float g_epT[BB*HH*NNV];
__device__ u64 g_argkey[BB];
__device__ unsigned g_count;

__device__ __forceinline__ unsigned f2ord(float v) {
    unsigned u = __float_as_uint(v);
    return (u & 0x80000000u) ? ~u : (u | 0x80000000u);
}
__device__ __forceinline__ u64 pack2(float x) {
    u64 r; asm("mov.b64 %0, {%1, %1};" : "=l"(r) : "f"(x)); return r;
}
__device__ __forceinline__ void ffma2(u64& d, u64 a, u64 b) {
    asm("fma.rn.f32x2 %0, %1, %2, %0;" : "+l"(d) : "l"(a), "l"(b));
}
__device__ __forceinline__ float2 unpk(u64 v) {
    float2 r; asm("mov.b64 {%0, %1}, %2;" : "=f"(r.x), "=f"(r.y) : "l"(v)); return r;
}

// grid barrier: monotonic arrival counter, release/acquire via __threadfence
__device__ __forceinline__ void gbar(unsigned expected) {
    __syncthreads();
    if (threadIdx.x == 0) {
        __threadfence();
        atomicAdd(&g_count, 1u);
        volatile unsigned* p = &g_count;
        while (*p < expected) { }
        __threadfence();
    }
    __syncthreads();
}

// As row-major [32][256]; coalesced fill
__device__ __forceinline__ void loadAr(const float* __restrict__ A, int lda, int k0,
                                       float* As) {
#pragma unroll
    for (int i = 0; i < 32; ++i)
        As[(i << 8) + threadIdx.x] = A[(size_t)i * lda + k0 + threadIdx.x];
}

#define KSTEP(AX0, AX1, WOFF) do { \
    ulonglong2 w_ = *reinterpret_cast<const ulonglong2*>(wp + (WOFF)); \
    u64 pa0_ = pack2(AX0), pa1_ = pack2(AX1); \
    ffma2(acc[0], pa0_, w_.x); ffma2(acc[1], pa0_, w_.y); \
    ffma2(acc[2], pa1_, w_.x); ffma2(acc[3], pa1_, w_.y); \
} while (0)

// 32x64 tile over 256 K. q col-quad, rows r0,r0+1. acc: {r0c01,r0c23,r1c01,r1c23}
__device__ __forceinline__ void mmaP(const float* __restrict__ W, int ldw, int col,
                                     const float* As, int r0, u64* acc) {
    const float4* A0 = reinterpret_cast<const float4*>(As + (r0 << 8));
    const float4* A1 = reinterpret_cast<const float4*>(As + ((r0 + 1) << 8));
    size_t ldb = (size_t)ldw * 4;
#pragma unroll 2
    for (int kk = 0; kk < 64; ++kk) {
        float4 a0 = A0[kk], a1 = A1[kk];
        const char* wp = reinterpret_cast<const char*>(W + col) + (size_t)(kk * 4) * ldb;
        KSTEP(a0.x, a1.x, 0);
        KSTEP(a0.y, a1.y, ldb);
        KSTEP(a0.z, a1.z, 2 * ldb);
        KSTEP(a0.w, a1.w, 3 * ldb);
    }
}

__device__ __forceinline__ void storeTile(float* out, int ldo, int j, int r0,
                                          const u64* acc) {
    float2 a = unpk(acc[0]), b = unpk(acc[1]), c = unpk(acc[2]), d = unpk(acc[3]);
    *reinterpret_cast<float4*>(out + (size_t)r0 * ldo + j) = make_float4(a.x, a.y, b.x, b.y);
    *reinterpret_cast<float4*>(out + (size_t)(r0 + 1) * ldo + j) = make_float4(c.x, c.y, d.x, d.y);
}

// ================= setup kernels =================
__global__ void kInit(const float* __restrict__ feat, const float* __restrict__ emb) {
    int gid = blockIdx.x * 256 + threadIdx.x, stride = gridDim.x * 256;
    for (int i = gid; i < BB*FF; i += stride) {
        int b = i / FF, j = i % FF;
        float s = 0.f;
        for (int n = 0; n < NNV; ++n) s += feat[((size_t)b*NNV + n)*FF + j];
        g_mean[i] = s * (1.f/64.f);
    }
    for (int i = gid; i < BB*EE; i += stride) {
        int b = i >> 9, e = i & 511;
        g_a2[b*A2K + e] = emb[(size_t)SOS_ID*EE + e];
    }
    if (gid < BB) g_argkey[gid] = 0ull;
    if (gid == 0) g_count = 0u;
}

__global__ void __launch_bounds__(256) kInitHC(const float* __restrict__ Wh,
                                               const float* __restrict__ Wc) {
    __shared__ float As[32*256];
    int mat = blockIdx.x >> 3, tile = blockIdx.x & 7;
    const float* W = mat ? Wc : Wh;
    float* out = mat ? g_c : g_h;
    int tid = threadIdx.x, q = tid & 15, r0 = (tid >> 4) * 2;
    int j = tile*64 + q*4;
    u64 acc[4] = {0,0,0,0};
    for (int k0 = 0; k0 < FF; k0 += 256) {
        __syncthreads();
        loadAr(g_mean, FF, k0, As);
        __syncthreads();
        mmaP(W + (size_t)k0 * HH, HH, j, As, r0, acc);
    }
    storeTile(out, HH, j, r0, acc);
}

__global__ void kHCBias(const float* __restrict__ bh, const float* __restrict__ bc) {
    int idx = blockIdx.x * 256 + threadIdx.x;
    int b = idx >> 9, u = idx & 511;
    float h = g_h[idx] + bh[u];
    g_h[idx] = h;
    g_a2[b*A2K + EF + u] = h;
    g_c[idx] += bc[u];
}

__global__ void __launch_bounds__(256) kEncProj(const float* __restrict__ feat,
                                                const float* __restrict__ W2,
                                                const float* __restrict__ b2) {
    __shared__ float As[128][65];
    int tid = threadIdx.x, rt = blockIdx.x, ct = blockIdx.y;
    int q = tid & 15, rr = tid >> 4;
    float acc[16];
#pragma unroll
    for (int i = 0; i < 16; ++i) acc[i] = 0.f;
    int row0 = rt * 64;
    for (int k0 = 0; k0 < FF; k0 += 128) {
        __syncthreads();
        for (int tt = tid; tt < 64*128; tt += 256) {
            int r = tt >> 7, k = tt & 127;
            As[k][r] = feat[(size_t)(row0 + r)*FF + k0 + k];
        }
        __syncthreads();
        const float* Wp = W2 + (size_t)k0 * HH + ct*64 + q*4;
#pragma unroll 4
        for (int k = 0; k < 128; ++k) {
            float4 w = *reinterpret_cast<const float4*>(Wp + (size_t)k * HH);
#pragma unroll
            for (int rrr = 0; rrr < 4; ++rrr) {
                float a = As[k][rr*4 + rrr];
                acc[rrr*4+0]=fmaf(a,w.x,acc[rrr*4+0]);
                acc[rrr*4+1]=fmaf(a,w.y,acc[rrr*4+1]);
                acc[rrr*4+2]=fmaf(a,w.z,acc[rrr*4+2]);
                acc[rrr*4+3]=fmaf(a,w.w,acc[rrr*4+3]);
            }
        }
    }
#pragma unroll
    for (int rrr = 0; rrr < 4; ++rrr) {
        int row = row0 + rr*4 + rrr;
        int b = row >> 6, nidx = row & 63;
#pragma unroll
        for (int cc = 0; cc < 4; ++cc) {
            int j = ct*64 + q*4 + cc;
            g_epT[((size_t)b*HH + j)*NNV + nidx] = acc[rrr*4+cc] + b2[j];
        }
    }
}

// setup: lin = h0 @ [W1 | Wg] (28 tiles)
__global__ void __launch_bounds__(256) kSetupLin(const float* __restrict__ W1,
                                                 const float* __restrict__ Wg) {
    __shared__ float As[32*256];
    int tid = threadIdx.x, q = tid & 15, r0 = (tid >> 4) * 2;
    int tile = blockIdx.x;
    int j = tile*64 + q*4;
    const float* W; int ldw, col;
    if (tile < 8) { W = W1; ldw = HH; col = j; }
    else          { W = Wg; ldw = FF; col = j - HH; }
    u64 acc[4] = {0,0,0,0};
    for (int k0 = 0; k0 < HH; k0 += 256) {
        __syncthreads();
        loadAr(g_h, HH, k0, As);
        __syncthreads();
        mmaP(W + (size_t)k0 * ldw, ldw, col, As, r0, acc);
    }
    storeTile(g_lin, EF, j, r0, acc);
}

// ================= persistent decode loop =================
__global__ void __launch_bounds__(256, 1) kLoop(
    const float* __restrict__ feat, const float* __restrict__ emb,
    const float* __restrict__ b1, const float* __restrict__ Va,
    const float* __restrict__ bVa, const float* __restrict__ bg,
    const float* __restrict__ Wx, const float* __restrict__ Whh,
    const float* __restrict__ blstm,
    const float* __restrict__ W1, const float* __restrict__ Wg,
    const float* __restrict__ Wout, const float* __restrict__ bout,
    float* __restrict__ dout)
{
    __shared__ float SA[32*256];
    __shared__ u64 skey[BB];
    int tid = threadIdx.x, blk = blockIdx.x;
    int q = tid & 15, r0 = (tid >> 4) * 2;
    unsigned bar = 0;

    for (int t = 0; t < TT; ++t) {
        // ---------- P1: attention(0-31) + emb gather(32-63) + gates h-chunks(64-127)
        if (blk < 32) {
            int b = blk;
            float* hq = SA; float* va = SA + 512;
            float* part = SA + 1024; float* wsh = SA + 1280; float* red = SA + 1344;
            for (int i = tid; i < HH; i += 256) {
                hq[i] = g_lin[b*EF + i] + b1[i];
                va[i] = Va[i];
            }
            __syncthreads();
            int n = tid & 63, p = tid >> 6;
            const float* ep = g_epT + (size_t)b * HH * NNV;
            float s = 0.f;
            for (int k = p*128; k < p*128 + 128; ++k)
                s = fmaf(fmaxf(hq[k] + ep[(size_t)k*NNV + n], 0.f), va[k], s);
            part[p*64 + n] = s;
            __syncthreads();
            float sc = -1e30f;
            if (tid < 64) sc = part[tid]+part[64+tid]+part[128+tid]+part[192+tid] + bVa[0];
            float m = sc;
#pragma unroll
            for (int d = 16; d >= 1; d >>= 1) m = fmaxf(m, __shfl_xor_sync(0xFFFFFFFFu, m, d));
            if (tid < 64 && (tid & 31) == 0) red[tid >> 5] = m;
            __syncthreads();
            float gm = fmaxf(red[0], red[1]);
            float e = (tid < 64) ? expf(sc - gm) : 0.f;
            float ss = e;
#pragma unroll
            for (int d = 16; d >= 1; d >>= 1) ss += __shfl_xor_sync(0xFFFFFFFFu, ss, d);
            if (tid < 64 && (tid & 31) == 0) red[2 + (tid >> 5)] = ss;
            __syncthreads();
            float tot = red[2] + red[3];
            if (tid < 64) {
                float w = e / tot;
                wsh[tid] = w;
                dout[DOUT_ATTN + (size_t)b*TT*NNV + (size_t)t*NNV + tid] = w;
            }
            __syncthreads();
#pragma unroll
            for (int ch = 0; ch < 5; ++ch) {
                int j = ch*256 + tid;
                const float* fb = feat + (size_t)b*NNV*FF + j;
                float cs = 0.f;
#pragma unroll 8
                for (int nn = 0; nn < NNV; ++nn) cs = fmaf(wsh[nn], fb[(size_t)nn*FF], cs);
                float gp = g_lin[b*EF + HH + j] + bg[j];
                float gate = 1.f / (1.f + expf(-gp));
                g_a2[b*A2K + EE + j] = cs * gate;
            }
        } else if (blk < 64) {
            if (t > 0) {
                int b = blk - 32;
                u64 key = g_argkey[b];
                int idx = (int)(~(unsigned)(key & 0xFFFFFFFFu));
                for (int e = tid; e < EE; e += 256)
                    g_a2[b*A2K + e] = emb[(size_t)idx*EE + e];
            }
        } else if (blk < 128) {
            int u = blk - 64;
            int ck = 7 + (u >> 5), tile = u & 31, k0 = ck << 8;
            __syncthreads();
            loadAr(g_a2, A2K, k0, SA);
            __syncthreads();
            u64 acc[4] = {0,0,0,0};
            int j = (tile << 6) + (q << 2);
            mmaP(Whh + (size_t)(k0 - EF) * G4H, G4H, j, SA, r0, acc);
            storeTile(g_gpart + (size_t)ck * BB * G4H, G4H, j, r0, acc);
        }
        gbar(++bar * NBLK);

        // ---------- P2: gates x + ctx chunks (ck 0..6), 224 units
        for (int u = blk; u < 224; u += NBLK) {
            int ck = u >> 5, tile = u & 31, k0 = ck << 8;
            __syncthreads();
            loadAr(g_a2, A2K, k0, SA);
            __syncthreads();
            u64 acc[4] = {0,0,0,0};
            int j = (tile << 6) + (q << 2);
            mmaP(Wx + (size_t)k0 * G4H, G4H, j, SA, r0, acc);
            storeTile(g_gpart + (size_t)ck * BB * G4H, G4H, j, r0, acc);
        }
        gbar(++bar * NBLK);

        // ---------- P3: LSTM elementwise (blocks 0-63) + argkey reset (block 64)
        if (blk < 64) {
            int idx = (blk << 8) + tid;
            int b = idx >> 9, u = idx & 511;
            float gv[4];
#pragma unroll
            for (int g = 0; g < 4; ++g) {
                int col = g*512 + u;
                float s = blstm[col];
#pragma unroll
                for (int ck = 0; ck < 9; ++ck)
                    s += g_gpart[(size_t)ck*BB*G4H + b*G4H + col];
                gv[g] = s;
            }
            float c = g_c[idx];
            float si = 1.f / (1.f + expf(-gv[0]));
            float sf = 1.f / (1.f + expf(-gv[1]));
            float so = 1.f / (1.f + expf(-gv[3]));
            float c2 = sf * c + si * tanhf(gv[2]);
            float h2 = so * tanhf(c2);
            g_c[idx] = c2;
            g_h[idx] = h2;
            g_a2[b*A2K + EF + u] = h2;
            if (t == TT-1) { dout[DOUT_H + idx] = h2; dout[DOUT_C + idx] = c2; }
        } else if (blk == 64 && tid < BB) {
            g_argkey[tid] = 0ull;
        }
        gbar(++bar * NBLK);

        // ---------- P4: logits+argmax (157) + lin for next step (28)
        for (int u = blk; u < NLOGIT_TILES + 28; u += NBLK) {
            if (u < NLOGIT_TILES) {
                __syncthreads();
                if (tid < BB) skey[tid] = 0ull;
                int jq = (u << 6) + (q << 2);
                bool jv = jq < VV;
                int colc = jv ? jq : 0;
                u64 acc[4] = {0,0,0,0};
                for (int k0 = 0; k0 < HH; k0 += 256) {
                    __syncthreads();
                    loadAr(g_h, HH, k0, SA);
                    __syncthreads();
                    mmaP(Wout + (size_t)k0 * VV, VV, colc, SA, r0, acc);
                }
                if (jv) {
                    float2 p01 = unpk(acc[0]), p23 = unpk(acc[1]);
                    float2 q01 = unpk(acc[2]), q23 = unpk(acc[3]);
                    float vr0[4] = {p01.x, p01.y, p23.x, p23.y};
                    float vr1[4] = {q01.x, q01.y, q23.x, q23.y};
                    u64 k0_ = 0ull, k1_ = 0ull;
#pragma unroll
                    for (int cc = 0; cc < 4; ++cc) {
                        int j = jq + cc;
                        float bo = bout[j];
                        float v0 = vr0[cc] + bo, v1 = vr1[cc] + bo;
                        dout[(size_t)r0*TT*VV + (size_t)t*VV + j] = v0;
                        dout[(size_t)(r0+1)*TT*VV + (size_t)t*VV + j] = v1;
                        u64 kk0 = ((u64)f2ord(v0) << 32) | (unsigned)(~j);
                        u64 kk1 = ((u64)f2ord(v1) << 32) | (unsigned)(~j);
                        if (kk0 > k0_) k0_ = kk0;
                        if (kk1 > k1_) k1_ = kk1;
                    }
                    atomicMax(&skey[r0], k0_);
                    atomicMax(&skey[r0+1], k1_);
                }
                __syncthreads();
                if (tid < BB && skey[tid]) atomicMax(&g_argkey[tid], skey[tid]);
            } else {
                int lt = u - NLOGIT_TILES;
                int j = (lt << 6) + (q << 2);
                const float* W; int ldw, col;
                if (lt < 8) { W = W1; ldw = HH; col = j; }
                else        { W = Wg; ldw = FF; col = j - HH; }
                u64 acc[4] = {0,0,0,0};
                for (int k0 = 0; k0 < HH; k0 += 256) {
                    __syncthreads();
                    loadAr(g_h, HH, k0, SA);
                    __syncthreads();
                    mmaP(W + (size_t)k0 * ldw, ldw, col, SA, r0, acc);
                }
                storeTile(g_lin, EF, j, r0, acc);
            }
        }
        gbar(++bar * NBLK);
    }
}

extern "C" void kernel_launch(void* const* d_in, const int* in_sizes, int n_in,
                              void* d_out, int out_size) {
    int base = (n_in >= 3 && in_sizes[2] == 1) ? 3 : 2;
    const float* feat = (const float*)d_in[0];
    const float* emb  = (const float*)d_in[base+0];
    const float* W1   = (const float*)d_in[base+1];
    const float* b1   = (const float*)d_in[base+2];
    const float* W2   = (const float*)d_in[base+3];
    const float* b2   = (const float*)d_in[base+4];
    const float* Va   = (const float*)d_in[base+5];
    const float* bVa  = (const float*)d_in[base+6];
    const float* Wh   = (const float*)d_in[base+7];
    const float* bh   = (const float*)d_in[base+8];
    const float* Wc   = (const float*)d_in[base+9];
    const float* bc   = (const float*)d_in[base+10];
    const float* Wg   = (const float*)d_in[base+11];
    const float* bg   = (const float*)d_in[base+12];
    const float* Wx   = (const float*)d_in[base+13];
    const float* Whh  = (const float*)d_in[base+14];
    const float* blstm= (const float*)d_in[base+15];
    const float* Wout = (const float*)d_in[base+16];
    const float* bout = (const float*)d_in[base+17];
    float* dout = (float*)d_out;

    kInit<<<160, 256>>>(feat, emb);
    kInitHC<<<16, 256>>>(Wh, Wc);
    kHCBias<<<64, 256>>>(bh, bc);
    kEncProj<<<dim3(32, 8), 256>>>(feat, W2, b2);
    kSetupLin<<<28, 256>>>(W1, Wg);
    kLoop<<<NBLK, 256>>>(feat, emb, b1, Va, bVa, bg, Wx, Whh, blstm,
                         W1, Wg, Wout, bout, dout);
}

// round 11
// speedup vs baseline: 1.2478x; 1.2404x over previous
#include <cuda_runtime.h>
#include <math.h>

#define BB   32
#define NNV  64
#define FF   1280
#define HH   512
#define EE   512
#define VV   10000
#define TT   80
#define SOS_ID 1
#define EF   1792
#define A2K  2304
#define G4H  2048
#define NBLK 148

#define DOUT_H    (BB*TT*VV)
#define DOUT_C    (DOUT_H + BB*HH)
#define DOUT_ATTN (DOUT_C + BB*HH)

#define NLOGIT_U 79   // 128-col logit tiles
#define NLIN_U   14   // 128-col lin tiles

typedef unsigned long long u64;

__device__ float g_h[BB*HH];
__device__ float g_c[BB*HH];
__device__ float g_a2[BB*A2K];            // [x 512 | ctx 1280 | h 512]
__device__ float g_lin[BB*EF];            // [h@W1 512 | h@Wg 1280]
__device__ float g_gpart[9*BB*G4H];
__device__ float g_mean[BB*FF];
__device__ float g_epT[BB*HH*NNV];
__device__ u64 g_argkey[BB];
__device__ unsigned g_count;

__device__ __forceinline__ unsigned f2ord(float v) {
    unsigned u = __float_as_uint(v);
    return (u & 0x80000000u) ? ~u : (u | 0x80000000u);
}
__device__ __forceinline__ u64 pack2(float x) {
    u64 r; asm("mov.b64 %0, {%1, %1};" : "=l"(r) : "f"(x)); return r;
}
__device__ __forceinline__ void ffma2(u64& d, u64 a, u64 b) {
    asm("fma.rn.f32x2 %0, %1, %2, %0;" : "+l"(d) : "l"(a), "l"(b));
}
__device__ __forceinline__ float2 unpk(u64 v) {
    float2 r; asm("mov.b64 {%0, %1}, %2;" : "=f"(r.x), "=f"(r.y) : "l"(v)); return r;
}

// grid barrier: monotonic arrival counter, release/acquire via __threadfence
__device__ __forceinline__ void gbar(unsigned expected) {
    __syncthreads();
    if (threadIdx.x == 0) {
        __threadfence();
        atomicAdd(&g_count, 1u);
        volatile unsigned* p = &g_count;
        while (*p < expected) { }
        __threadfence();
    }
    __syncthreads();
}

// As row-major [32][256]
template <int NT>
__device__ __forceinline__ void loadAr(const float* __restrict__ A, int lda, int k0,
                                       float* As) {
#pragma unroll
    for (int i = 0; i < 8192 / NT; ++i) {
        int e = i * NT + threadIdx.x;
        As[e] = A[(size_t)(e >> 8) * lda + k0 + (e & 255)];
    }
}

#define CSTEP(AX0, AX1, WW) do { \
    u64 pa0_ = pack2(AX0), pa1_ = pack2(AX1); \
    ffma2(acc[0], pa0_, (WW).x); ffma2(acc[1], pa0_, (WW).y); \
    ffma2(acc[2], pa1_, (WW).x); ffma2(acc[3], pa1_, (WW).y); \
} while (0)

// 32-row x 4-col strip over 256 K, W double-buffered in registers.
// acc: {r0c01, r0c23, r1c01, r1c23}
__device__ __forceinline__ void mmaP(const float* __restrict__ W, int ldw, int col,
                                     const float* As, int r0, u64* acc) {
    const float4* A0 = reinterpret_cast<const float4*>(As + (r0 << 8));
    const float4* A1 = reinterpret_cast<const float4*>(As + ((r0 + 1) << 8));
    const char* wp = reinterpret_cast<const char*>(W + col);
    size_t ldb = (size_t)ldw * 4;
    ulonglong2 w0 = *reinterpret_cast<const ulonglong2*>(wp);
    ulonglong2 w1 = *reinterpret_cast<const ulonglong2*>(wp + ldb);
    ulonglong2 w2 = *reinterpret_cast<const ulonglong2*>(wp + 2 * ldb);
    ulonglong2 w3 = *reinterpret_cast<const ulonglong2*>(wp + 3 * ldb);
#pragma unroll 4
    for (int kk = 0; kk < 64; ++kk) {
        float4 a0 = A0[kk], a1 = A1[kk];
        ulonglong2 c0 = w0, c1 = w1, c2 = w2, c3 = w3;
        if (kk < 63) {
            const char* wn = wp + (size_t)((kk + 1) * 4) * ldb;
            w0 = *reinterpret_cast<const ulonglong2*>(wn);
            w1 = *reinterpret_cast<const ulonglong2*>(wn + ldb);
            w2 = *reinterpret_cast<const ulonglong2*>(wn + 2 * ldb);
            w3 = *reinterpret_cast<const ulonglong2*>(wn + 3 * ldb);
        }
        CSTEP(a0.x, a1.x, c0);
        CSTEP(a0.y, a1.y, c1);
        CSTEP(a0.z, a1.z, c2);
        CSTEP(a0.w, a1.w, c3);
    }
}

__device__ __forceinline__ void storeTile(float* out, int ldo, int j, int r0,
                                          const u64* acc) {
    float2 a = unpk(acc[0]), b = unpk(acc[1]), c = unpk(acc[2]), d = unpk(acc[3]);
    *reinterpret_cast<float4*>(out + (size_t)r0 * ldo + j) = make_float4(a.x, a.y, b.x, b.y);
    *reinterpret_cast<float4*>(out + (size_t)(r0 + 1) * ldo + j) = make_float4(c.x, c.y, d.x, d.y);
}

// ================= setup kernels =================
__global__ void kInit(const float* __restrict__ feat, const float* __restrict__ emb) {
    int gid = blockIdx.x * 256 + threadIdx.x, stride = gridDim.x * 256;
    for (int i = gid; i < BB*FF; i += stride) {
        int b = i / FF, j = i % FF;
        float s = 0.f;
        for (int n = 0; n < NNV; ++n) s += feat[((size_t)b*NNV + n)*FF + j];
        g_mean[i] = s * (1.f/64.f);
    }
    for (int i = gid; i < BB*EE; i += stride) {
        int b = i >> 9, e = i & 511;
        g_a2[b*A2K + e] = emb[(size_t)SOS_ID*EE + e];
    }
    if (gid < BB) g_argkey[gid] = 0ull;
    if (gid == 0) g_count = 0u;
}

__global__ void __launch_bounds__(256) kInitHC(const float* __restrict__ Wh,
                                               const float* __restrict__ Wc) {
    __shared__ float As[32*256];
    int mat = blockIdx.x >> 3, tile = blockIdx.x & 7;
    const float* W = mat ? Wc : Wh;
    float* out = mat ? g_c : g_h;
    int tid = threadIdx.x, q = tid & 15, r0 = (tid >> 4) * 2;
    int j = tile*64 + q*4;
    u64 acc[4] = {0,0,0,0};
    for (int k0 = 0; k0 < FF; k0 += 256) {
        __syncthreads();
        loadAr<256>(g_mean, FF, k0, As);
        __syncthreads();
        mmaP(W + (size_t)k0 * HH, HH, j, As, r0, acc);
    }
    storeTile(out, HH, j, r0, acc);
}

__global__ void kHCBias(const float* __restrict__ bh, const float* __restrict__ bc) {
    int idx = blockIdx.x * 256 + threadIdx.x;
    int b = idx >> 9, u = idx & 511;
    float h = g_h[idx] + bh[u];
    g_h[idx] = h;
    g_a2[b*A2K + EF + u] = h;
    g_c[idx] += bc[u];
}

__global__ void __launch_bounds__(256) kEncProj(const float* __restrict__ feat,
                                                const float* __restrict__ W2,
                                                const float* __restrict__ b2) {
    __shared__ float As[128][65];
    int tid = threadIdx.x, rt = blockIdx.x, ct = blockIdx.y;
    int q = tid & 15, rr = tid >> 4;
    u64 acc[8] = {0,0,0,0,0,0,0,0};
    int row0 = rt * 64;
    for (int k0 = 0; k0 < FF; k0 += 128) {
        __syncthreads();
        for (int tt = tid; tt < 64*128; tt += 256) {
            int r = tt >> 7, k = tt & 127;
            As[k][r] = feat[(size_t)(row0 + r)*FF + k0 + k];
        }
        __syncthreads();
        const char* Wp = reinterpret_cast<const char*>(W2 + (size_t)k0 * HH + ct*64 + q*4);
#pragma unroll 4
        for (int k = 0; k < 128; ++k) {
            ulonglong2 w = *reinterpret_cast<const ulonglong2*>(Wp + (size_t)k * HH * 4);
#pragma unroll
            for (int rrr = 0; rrr < 4; ++rrr) {
                u64 pa = pack2(As[k][rr*4 + rrr]);
                ffma2(acc[rrr*2],     pa, w.x);
                ffma2(acc[rrr*2 + 1], pa, w.y);
            }
        }
    }
#pragma unroll
    for (int rrr = 0; rrr < 4; ++rrr) {
        int row = row0 + rr*4 + rrr;
        int b = row >> 6, nidx = row & 63;
        float2 lo = unpk(acc[rrr*2]), hi = unpk(acc[rrr*2 + 1]);
        float v[4] = {lo.x, lo.y, hi.x, hi.y};
#pragma unroll
        for (int cc = 0; cc < 4; ++cc) {
            int j = ct*64 + q*4 + cc;
            g_epT[((size_t)b*HH + j)*NNV + nidx] = v[cc] + b2[j];
        }
    }
}

// setup: lin = h0 @ [W1 | Wg] (28 x 64-col tiles)
__global__ void __launch_bounds__(256) kSetupLin(const float* __restrict__ W1,
                                                 const float* __restrict__ Wg) {
    __shared__ float As[32*256];
    int tid = threadIdx.x, q = tid & 15, r0 = (tid >> 4) * 2;
    int tile = blockIdx.x;
    int j = tile*64 + q*4;
    const float* W; int ldw, col;
    if (tile < 8) { W = W1; ldw = HH; col = j; }
    else          { W = Wg; ldw = FF; col = j - HH; }
    u64 acc[4] = {0,0,0,0};
    for (int k0 = 0; k0 < HH; k0 += 256) {
        __syncthreads();
        loadAr<256>(g_h, HH, k0, As);
        __syncthreads();
        mmaP(W + (size_t)k0 * ldw, ldw, col, As, r0, acc);
    }
    storeTile(g_lin, EF, j, r0, acc);
}

// ================= persistent decode loop: 148 blocks x 512 threads =================
__global__ void __launch_bounds__(512, 1) kLoop(
    const float* __restrict__ feat, const float* __restrict__ emb,
    const float* __restrict__ b1, const float* __restrict__ Va,
    const float* __restrict__ bVa, const float* __restrict__ bg,
    const float* __restrict__ Wx, const float* __restrict__ Whh,
    const float* __restrict__ blstm,
    const float* __restrict__ W1, const float* __restrict__ Wg,
    const float* __restrict__ Wout, const float* __restrict__ bout,
    float* __restrict__ dout)
{
    __shared__ float SA[32*256];
    __shared__ u64 skey[BB];
    int tid = threadIdx.x, blk = blockIdx.x;
    int q = tid & 31, r0 = (tid >> 5) * 2;   // 32 col-quads (128 cols), 16 row-pairs
    unsigned bar = 0;

    for (int t = 0; t < TT; ++t) {
        // ---------- P1: attention(0-31) | emb gather(32-63) | gates h-chunks(64-95)
        if (blk < 32) {
            int b = blk;
            float* hq = SA; float* va = SA + 512;
            float* part = SA + 1024; float* wsh = SA + 1536; float* red = SA + 1600;
            for (int i = tid; i < HH; i += 512) {
                hq[i] = g_lin[b*EF + i] + b1[i];
                va[i] = Va[i];
            }
            __syncthreads();
            int n = tid & 63, p = tid >> 6;       // 8 k-partitions of 64
            const float* ep = g_epT + (size_t)b * HH * NNV;
            float s = 0.f;
            for (int k = p*64; k < p*64 + 64; ++k)
                s = fmaf(fmaxf(hq[k] + ep[(size_t)k*NNV + n], 0.f), va[k], s);
            part[p*64 + n] = s;
            __syncthreads();
            float sc = -1e30f;
            if (tid < 64) {
                sc = bVa[0];
#pragma unroll
                for (int p2 = 0; p2 < 8; ++p2) sc += part[p2*64 + tid];
            }
            float m = sc;
#pragma unroll
            for (int d = 16; d >= 1; d >>= 1) m = fmaxf(m, __shfl_xor_sync(0xFFFFFFFFu, m, d));
            if (tid < 64 && (tid & 31) == 0) red[tid >> 5] = m;
            __syncthreads();
            float gm = fmaxf(red[0], red[1]);
            float e = (tid < 64) ? expf(sc - gm) : 0.f;
            float ss = e;
#pragma unroll
            for (int d = 16; d >= 1; d >>= 1) ss += __shfl_xor_sync(0xFFFFFFFFu, ss, d);
            if (tid < 64 && (tid & 31) == 0) red[2 + (tid >> 5)] = ss;
            __syncthreads();
            float tot = red[2] + red[3];
            if (tid < 64) {
                float w = e / tot;
                wsh[tid] = w;
                dout[DOUT_ATTN + (size_t)b*TT*NNV + (size_t)t*NNV + tid] = w;
            }
            __syncthreads();
            for (int j = tid; j < FF; j += 512) {
                const float* fb = feat + (size_t)b*NNV*FF + j;
                float cs = 0.f;
#pragma unroll 8
                for (int nn = 0; nn < NNV; ++nn) cs = fmaf(wsh[nn], fb[(size_t)nn*FF], cs);
                float gp = g_lin[b*EF + HH + j] + bg[j];
                float gate = 1.f / (1.f + expf(-gp));
                g_a2[b*A2K + EE + j] = cs * gate;
            }
        } else if (blk < 64) {
            if (t > 0) {
                int b = blk - 32;
                u64 key = g_argkey[b];
                int idx = (int)(~(unsigned)(key & 0xFFFFFFFFu));
                for (int e = tid; e < EE; e += 512)
                    g_a2[b*A2K + e] = emb[(size_t)idx*EE + e];
            }
        } else if (blk < 96) {
            int u = blk - 64;                   // 0..31
            int ck = 7 + (u >> 4), tile = u & 15, k0 = ck << 8;
            __syncthreads();
            loadAr<512>(g_a2, A2K, k0, SA);
            __syncthreads();
            u64 acc[4] = {0,0,0,0};
            int j = (tile << 7) + (q << 2);
            mmaP(Whh + (size_t)(k0 - EF) * G4H, G4H, j, SA, r0, acc);
            storeTile(g_gpart + (size_t)ck * BB * G4H, G4H, j, r0, acc);
        }
        gbar(++bar * NBLK);

        // ---------- P2: Wx gates chunks (ck 0..6), 112 units, 1 round
        if (blk < 112) {
            int ck = blk >> 4, tile = blk & 15, k0 = ck << 8;
            __syncthreads();
            loadAr<512>(g_a2, A2K, k0, SA);
            __syncthreads();
            u64 acc[4] = {0,0,0,0};
            int j = (tile << 7) + (q << 2);
            mmaP(Wx + (size_t)k0 * G4H, G4H, j, SA, r0, acc);
            storeTile(g_gpart + (size_t)ck * BB * G4H, G4H, j, r0, acc);
        }
        gbar(++bar * NBLK);

        // ---------- P3: LSTM elementwise (blocks 0-31) + argkey reset (block 32)
        if (blk < 32) {
            int idx = (blk << 9) + tid;
            int b = idx >> 9, u = idx & 511;
            float gv[4];
#pragma unroll
            for (int g = 0; g < 4; ++g) {
                int col = g*512 + u;
                float s = blstm[col];
#pragma unroll
                for (int ck = 0; ck < 9; ++ck)
                    s += g_gpart[(size_t)ck*BB*G4H + b*G4H + col];
                gv[g] = s;
            }
            float c = g_c[idx];
            float si = 1.f / (1.f + expf(-gv[0]));
            float sf = 1.f / (1.f + expf(-gv[1]));
            float so = 1.f / (1.f + expf(-gv[3]));
            float c2 = sf * c + si * tanhf(gv[2]);
            float h2 = so * tanhf(c2);
            g_c[idx] = c2;
            g_h[idx] = h2;
            g_a2[b*A2K + EF + u] = h2;
            if (t == TT-1) { dout[DOUT_H + idx] = h2; dout[DOUT_C + idx] = c2; }
        } else if (blk == 32 && tid < BB) {
            g_argkey[tid] = 0ull;
        }
        gbar(++bar * NBLK);

        // ---------- P4: logits+argmax (79 units) + lin next step (14 units), 1 round
        if (blk < NLOGIT_U) {
            __syncthreads();
            if (tid < BB) skey[tid] = 0ull;
            int jq = (blk << 7) + (q << 2);
            bool jv = jq < VV;
            int colc = jv ? jq : 0;
            u64 acc[4] = {0,0,0,0};
            for (int k0 = 0; k0 < HH; k0 += 256) {
                __syncthreads();
                loadAr<512>(g_h, HH, k0, SA);
                __syncthreads();
                mmaP(Wout + (size_t)k0 * VV, VV, colc, SA, r0, acc);
            }
            if (jv) {
                float2 p01 = unpk(acc[0]), p23 = unpk(acc[1]);
                float2 q01 = unpk(acc[2]), q23 = unpk(acc[3]);
                float vr0[4] = {p01.x, p01.y, p23.x, p23.y};
                float vr1[4] = {q01.x, q01.y, q23.x, q23.y};
                u64 k0_ = 0ull, k1_ = 0ull;
#pragma unroll
                for (int cc = 0; cc < 4; ++cc) {
                    int j = jq + cc;
                    float bo = bout[j];
                    float v0 = vr0[cc] + bo, v1 = vr1[cc] + bo;
                    dout[(size_t)r0*TT*VV + (size_t)t*VV + j] = v0;
                    dout[(size_t)(r0+1)*TT*VV + (size_t)t*VV + j] = v1;
                    u64 kk0 = ((u64)f2ord(v0) << 32) | (unsigned)(~j);
                    u64 kk1 = ((u64)f2ord(v1) << 32) | (unsigned)(~j);
                    if (kk0 > k0_) k0_ = kk0;
                    if (kk1 > k1_) k1_ = kk1;
                }
                atomicMax(&skey[r0], k0_);
                atomicMax(&skey[r0+1], k1_);
            }
            __syncthreads();
            if (tid < BB && skey[tid]) atomicMax(&g_argkey[tid], skey[tid]);
        } else if (blk < NLOGIT_U + NLIN_U) {
            int lt = blk - NLOGIT_U;
            int j = (lt << 7) + (q << 2);
            const float* W; int ldw, col;
            if (lt < 4) { W = W1; ldw = HH; col = j; }
            else        { W = Wg; ldw = FF; col = j - HH; }
            u64 acc[4] = {0,0,0,0};
            for (int k0 = 0; k0 < HH; k0 += 256) {
                __syncthreads();
                loadAr<512>(g_h, HH, k0, SA);
                __syncthreads();
                mmaP(W + (size_t)k0 * ldw, ldw, col, SA, r0, acc);
            }
            storeTile(g_lin, EF, j, r0, acc);
        }
        gbar(++bar * NBLK);
    }
}

extern "C" void kernel_launch(void* const* d_in, const int* in_sizes, int n_in,
                              void* d_out, int out_size) {
    int base = (n_in >= 3 && in_sizes[2] == 1) ? 3 : 2;
    const float* feat = (const float*)d_in[0];
    const float* emb  = (const float*)d_in[base+0];
    const float* W1   = (const float*)d_in[base+1];
    const float* b1   = (const float*)d_in[base+2];
    const float* W2   = (const float*)d_in[base+3];
    const float* b2   = (const float*)d_in[base+4];
    const float* Va   = (const float*)d_in[base+5];
    const float* bVa  = (const float*)d_in[base+6];
    const float* Wh   = (const float*)d_in[base+7];
    const float* bh   = (const float*)d_in[base+8];
    const float* Wc   = (const float*)d_in[base+9];
    const float* bc   = (const float*)d_in[base+10];
    const float* Wg   = (const float*)d_in[base+11];
    const float* bg   = (const float*)d_in[base+12];
    const float* Wx   = (const float*)d_in[base+13];
    const float* Whh  = (const float*)d_in[base+14];
    const float* blstm= (const float*)d_in[base+15];
    const float* Wout = (const float*)d_in[base+16];
    const float* bout = (const float*)d_in[base+17];
    float* dout = (float*)d_out;

    kInit<<<160, 256>>>(feat, emb);
    kInitHC<<<16, 256>>>(Wh, Wc);
    kHCBias<<<64, 256>>>(bh, bc);
    kEncProj<<<dim3(32, 8), 256>>>(feat, W2, b2);
    kSetupLin<<<28, 256>>>(W1, Wg);
    kLoop<<<NBLK, 512>>>(feat, emb, b1, Va, bVa, bg, Wx, Whh, blstm,
                         W1, Wg, Wout, bout, dout);
}